// round 1
// baseline (speedup 1.0000x reference)
#include <cuda_runtime.h>
#include <cuda_bf16.h>
#include <math.h>

#define Tn   128
#define Bn   64
#define Hn   1024
#define NUn  256
#define Vn   8000
#define FH   4096   // 4*H

// ------------------------------ scratch (device globals, no allocs) -------
__device__ float g_X[Tn * Bn * NUn];      // embedded inputs, time-major rows (t*64+b)
__device__ float g_GX0[Tn * Bn * FH];     // X@Wx0, then normalized in place (gx0*(x-m)*rstd)
__device__ float g_h0[2][Bn * Hn];        // ping-pong h state layer 0
__device__ float g_c0[Bn * Hn];
__device__ float g_h1[2][Bn * Hn];        // ping-pong h state layer 1
__device__ float g_c1[Bn * Hn];
__device__ float g_H1[Bn * Tn * Hn];      // h1 history in OUTPUT row order (b*T + t)
__device__ float g_Y[Bn * Tn * NUn];      // projection output

__device__ __forceinline__ float sigm(float x) { return 1.0f / (1.0f + expf(-x)); }

// ------------------------------ init: zero recurrent state ----------------
__global__ void k_init() {
    int i = blockIdx.x * 256 + threadIdx.x;   // 65536 threads
    g_h0[0][i] = 0.f; g_h0[1][i] = 0.f; g_c0[i] = 0.f;
    g_h1[0][i] = 0.f; g_h1[1][i] = 0.f; g_c1[i] = 0.f;
}

// ------------------------------ embedding gather --------------------------
__global__ void k_embed(const int* __restrict__ inp, const float* __restrict__ emb) {
    int bid = blockIdx.x;             // t*Bn + b
    int t = bid >> 6, b = bid & 63;
    int u = threadIdx.x;              // 256
    int idx = inp[b * Tn + t];
    g_X[bid * NUn + u] = emb[idx * NUn + u];
}

// ------------------------------ generic fp32 GEMM (+bias) -----------------
// C[M,N] = A[M,K] @ B[K,N] (+ bias[N]).  BM=128, BN=64, BK=32, 256 threads,
// 8x4 per thread. All problem dims divide the tile sizes exactly.
__global__ void k_gemm(const float* __restrict__ A, const float* __restrict__ B,
                       const float* __restrict__ bias, float* __restrict__ C,
                       int M, int N, int K) {
    __shared__ float As[32][129];   // [k][m], padded
    __shared__ float Bs[32][64];    // [k][n]
    int tid = threadIdx.x;
    int bm = blockIdx.y * 128, bn = blockIdx.x * 64;
    int tx = tid & 15;              // col group (4 cols)
    int ty = tid >> 4;              // row group (8 rows)
    float acc[8][4] = {};

    for (int k0 = 0; k0 < K; k0 += 32) {
#pragma unroll
        for (int i = 0; i < 16; i++) {
            int idx = tid + i * 256;          // 0..4095
            int m = idx >> 5, k = idx & 31;
            As[k][m] = A[(long)(bm + m) * K + k0 + k];
        }
#pragma unroll
        for (int i = 0; i < 8; i++) {
            int idx = tid + i * 256;          // 0..2047
            int k = idx >> 6, n = idx & 63;
            Bs[k][n] = B[(long)(k0 + k) * N + bn + n];
        }
        __syncthreads();
#pragma unroll
        for (int k = 0; k < 32; k++) {
            float b4[4];
#pragma unroll
            for (int j = 0; j < 4; j++) b4[j] = Bs[k][tx * 4 + j];
#pragma unroll
            for (int i = 0; i < 8; i++) {
                float a = As[k][ty * 8 + i];
#pragma unroll
                for (int j = 0; j < 4; j++) acc[i][j] += a * b4[j];
            }
        }
        __syncthreads();
    }
#pragma unroll
    for (int i = 0; i < 8; i++) {
        int m = bm + ty * 8 + i;
#pragma unroll
        for (int j = 0; j < 4; j++) {
            int n = bn + tx * 4 + j;
            float v = acc[i][j] + (bias ? bias[n] : 0.f);
            C[(long)m * N + n] = v;
        }
    }
}

// ------------------------------ BN of X@Wx0, in place ---------------------
// One thread per (t, gate-col): batch mean/var over the 64 rows of that
// timestep, then writes gx0*(x-m)*rsqrt(v+eps) back in place.
__global__ void k_bnx(const float* __restrict__ gx0) {
    int idx = blockIdx.x * 256 + threadIdx.x;   // t*4096 + c, total 524288
    int t = idx >> 12, c = idx & 4095;
    int base = (t * 64) * FH + c;
    float s = 0.f, s2 = 0.f;
#pragma unroll
    for (int b = 0; b < 64; b++) {
        float v = g_GX0[base + b * FH];
        s += v; s2 += v * v;
    }
    float m = s * (1.f / 64.f);
    float var = fmaxf(s2 * (1.f / 64.f) - m * m, 0.f);
    float scl = gx0[c] * rsqrtf(var + 1e-5f);
#pragma unroll
    for (int b = 0; b < 64; b++) {
        g_GX0[base + b * FH] = scl * (g_GX0[base + b * FH] - m);
    }
}

// ------------------------------ layer-0 step ------------------------------
// grid 128 CTAs, 256 threads. CTA owns h-cols [cta*8, cta*8+8) and the four
// corresponding gate column groups. Fuses GEMM (h0@Wh0 slice), batch-norm
// (CTA-local over the 64 batch rows), gates, c-BN, h update.
__global__ void k_step0(int t, const float* __restrict__ Wh0, const float* __restrict__ b0,
                        const float* __restrict__ gh0, const float* __restrict__ gc0,
                        const float* __restrict__ bc0) {
    const int cta = blockIdx.x;
    const int tid = threadIdx.x;
    const int hc0 = cta * 8;
    const float* hin = g_h0[t & 1];
    float* hout = g_h0[(t + 1) & 1];

    __shared__ float As[32][65];        // h tile [k][r]
    __shared__ float Ws[32][32];        // weight tile [k][c]
    __shared__ float Gs[64][33];        // GEMM result [r][c]
    __shared__ float mh[32], sh[32];
    __shared__ float CsS[64][9], OsS[64][9];
    __shared__ float mc[8], scC[8];

    int tx = tid & 15;                  // col pair
    int ty = tid >> 4;                  // row quad (0..15)
    float acc[4][2] = {};

    for (int k0 = 0; k0 < Hn; k0 += 32) {
#pragma unroll
        for (int i = 0; i < 8; i++) {
            int idx = tid + i * 256;    // 0..2047
            int r = idx >> 5, k = idx & 31;
            As[k][r] = hin[r * Hn + k0 + k];
        }
#pragma unroll
        for (int i = 0; i < 4; i++) {
            int idx = tid + i * 256;    // 0..1023
            int k = idx >> 5, c = idx & 31;
            int col = (c >> 3) * Hn + hc0 + (c & 7);
            Ws[k][c] = Wh0[(k0 + k) * FH + col];
        }
        __syncthreads();
#pragma unroll
        for (int k = 0; k < 32; k++) {
            float w0 = Ws[k][tx * 2], w1 = Ws[k][tx * 2 + 1];
#pragma unroll
            for (int i = 0; i < 4; i++) {
                float a = As[k][ty * 4 + i];
                acc[i][0] += a * w0;
                acc[i][1] += a * w1;
            }
        }
        __syncthreads();
    }
#pragma unroll
    for (int i = 0; i < 4; i++) {
        Gs[ty * 4 + i][tx * 2]     = acc[i][0];
        Gs[ty * 4 + i][tx * 2 + 1] = acc[i][1];
    }
    __syncthreads();

    if (tid < 32) {
        float s = 0.f, s2 = 0.f;
#pragma unroll
        for (int r = 0; r < 64; r++) { float v = Gs[r][tid]; s += v; s2 += v * v; }
        float m = s * (1.f / 64.f);
        float var = fmaxf(s2 * (1.f / 64.f) - m * m, 0.f);
        int col = (tid >> 3) * Hn + hc0 + (tid & 7);
        mh[tid] = m;
        sh[tid] = gh0[col] * rsqrtf(var + 1e-5f);
    }
    __syncthreads();

    for (int it = tid; it < 512; it += 256) {
        int r = it & 63, j = it >> 6;
        int colh = hc0 + j;
        int base = (t * 64 + r) * FH;
        float preI = g_GX0[base + colh]          + sh[j]      * (Gs[r][j]      - mh[j])      + b0[colh];
        float preJ = g_GX0[base + Hn + colh]     + sh[8 + j]  * (Gs[r][8 + j]  - mh[8 + j])  + b0[Hn + colh];
        float preF = g_GX0[base + 2 * Hn + colh] + sh[16 + j] * (Gs[r][16 + j] - mh[16 + j]) + b0[2 * Hn + colh];
        float preO = g_GX0[base + 3 * Hn + colh] + sh[24 + j] * (Gs[r][24 + j] - mh[24 + j]) + b0[3 * Hn + colh];
        float cold = g_c0[r * Hn + colh];
        float cnew = sigm(preF + 1.f) * cold + sigm(preI) * tanhf(preJ);
        g_c0[r * Hn + colh] = cnew;
        CsS[r][j] = cnew;
        OsS[r][j] = preO;
    }
    __syncthreads();

    if (tid < 8) {
        float s = 0.f, s2 = 0.f;
#pragma unroll
        for (int r = 0; r < 64; r++) { float v = CsS[r][tid]; s += v; s2 += v * v; }
        float m = s * (1.f / 64.f);
        float var = fmaxf(s2 * (1.f / 64.f) - m * m, 0.f);
        mc[tid] = m;
        scC[tid] = rsqrtf(var + 1e-5f);
    }
    __syncthreads();

    for (int it = tid; it < 512; it += 256) {
        int r = it & 63, j = it >> 6;
        int colh = hc0 + j;
        float cn = gc0[colh] * (CsS[r][j] - mc[j]) * scC[j] + bc0[colh];
        hout[r * Hn + colh] = sigm(OsS[r][j]) * tanhf(cn);
    }
}

// ------------------------------ layer-1 step ------------------------------
// Same structure, two fused GEMMs (h0_new@Wx1 and h1@Wh1), each with its own
// batch-norm, then gates. Writes h1 ping-pong state AND the h1 history in
// output row order.
__global__ void k_step1(int t, const float* __restrict__ Wx1, const float* __restrict__ Wh1,
                        const float* __restrict__ b1, const float* __restrict__ gx1,
                        const float* __restrict__ gh1, const float* __restrict__ gc1,
                        const float* __restrict__ bc1) {
    const int cta = blockIdx.x;
    const int tid = threadIdx.x;
    const int hc0 = cta * 8;
    const float* h0in = g_h0[(t + 1) & 1];   // written by k_step0(t)
    const float* h1in = g_h1[t & 1];
    float* h1out = g_h1[(t + 1) & 1];

    __shared__ float As[32][65];        // h0 tile [k][r]
    __shared__ float Hs[32][65];        // h1 tile [k][r]
    __shared__ float Wa[32][32];        // Wx1 tile
    __shared__ float Wb[32][32];        // Wh1 tile
    __shared__ float GA[64][33], GB[64][33];
    __shared__ float ma[32], sa[32], mb[32], sb[32];
    __shared__ float CsS[64][9], OsS[64][9];
    __shared__ float mc[8], scC[8];

    int tx = tid & 15;
    int ty = tid >> 4;
    float accA[4][2] = {}, accB[4][2] = {};

    for (int k0 = 0; k0 < Hn; k0 += 32) {
#pragma unroll
        for (int i = 0; i < 8; i++) {
            int idx = tid + i * 256;
            int r = idx >> 5, k = idx & 31;
            As[k][r] = h0in[r * Hn + k0 + k];
            Hs[k][r] = h1in[r * Hn + k0 + k];
        }
#pragma unroll
        for (int i = 0; i < 4; i++) {
            int idx = tid + i * 256;
            int k = idx >> 5, c = idx & 31;
            int col = (c >> 3) * Hn + hc0 + (c & 7);
            Wa[k][c] = Wx1[(k0 + k) * FH + col];
            Wb[k][c] = Wh1[(k0 + k) * FH + col];
        }
        __syncthreads();
#pragma unroll
        for (int k = 0; k < 32; k++) {
            float wa0 = Wa[k][tx * 2], wa1 = Wa[k][tx * 2 + 1];
            float wb0 = Wb[k][tx * 2], wb1 = Wb[k][tx * 2 + 1];
#pragma unroll
            for (int i = 0; i < 4; i++) {
                float a = As[k][ty * 4 + i];
                float h = Hs[k][ty * 4 + i];
                accA[i][0] += a * wa0; accA[i][1] += a * wa1;
                accB[i][0] += h * wb0; accB[i][1] += h * wb1;
            }
        }
        __syncthreads();
    }
#pragma unroll
    for (int i = 0; i < 4; i++) {
        GA[ty * 4 + i][tx * 2]     = accA[i][0];
        GA[ty * 4 + i][tx * 2 + 1] = accA[i][1];
        GB[ty * 4 + i][tx * 2]     = accB[i][0];
        GB[ty * 4 + i][tx * 2 + 1] = accB[i][1];
    }
    __syncthreads();

    if (tid < 64) {
        int c = tid & 31, which = tid >> 5;
        float s = 0.f, s2 = 0.f;
        if (which == 0) {
#pragma unroll
            for (int r = 0; r < 64; r++) { float v = GA[r][c]; s += v; s2 += v * v; }
        } else {
#pragma unroll
            for (int r = 0; r < 64; r++) { float v = GB[r][c]; s += v; s2 += v * v; }
        }
        float m = s * (1.f / 64.f);
        float var = fmaxf(s2 * (1.f / 64.f) - m * m, 0.f);
        int col = (c >> 3) * Hn + hc0 + (c & 7);
        if (which == 0) { ma[c] = m; sa[c] = gx1[col] * rsqrtf(var + 1e-5f); }
        else            { mb[c] = m; sb[c] = gh1[col] * rsqrtf(var + 1e-5f); }
    }
    __syncthreads();

    for (int it = tid; it < 512; it += 256) {
        int r = it & 63, j = it >> 6;
        int colh = hc0 + j;
        float preI = sa[j]      * (GA[r][j]      - ma[j])      + sb[j]      * (GB[r][j]      - mb[j])      + b1[colh];
        float preJ = sa[8 + j]  * (GA[r][8 + j]  - ma[8 + j])  + sb[8 + j]  * (GB[r][8 + j]  - mb[8 + j])  + b1[Hn + colh];
        float preF = sa[16 + j] * (GA[r][16 + j] - ma[16 + j]) + sb[16 + j] * (GB[r][16 + j] - mb[16 + j]) + b1[2 * Hn + colh];
        float preO = sa[24 + j] * (GA[r][24 + j] - ma[24 + j]) + sb[24 + j] * (GB[r][24 + j] - mb[24 + j]) + b1[3 * Hn + colh];
        float cold = g_c1[r * Hn + colh];
        float cnew = sigm(preF + 1.f) * cold + sigm(preI) * tanhf(preJ);
        g_c1[r * Hn + colh] = cnew;
        CsS[r][j] = cnew;
        OsS[r][j] = preO;
    }
    __syncthreads();

    if (tid < 8) {
        float s = 0.f, s2 = 0.f;
#pragma unroll
        for (int r = 0; r < 64; r++) { float v = CsS[r][tid]; s += v; s2 += v * v; }
        float m = s * (1.f / 64.f);
        float var = fmaxf(s2 * (1.f / 64.f) - m * m, 0.f);
        mc[tid] = m;
        scC[tid] = rsqrtf(var + 1e-5f);
    }
    __syncthreads();

    for (int it = tid; it < 512; it += 256) {
        int r = it & 63, j = it >> 6;
        int colh = hc0 + j;
        float cn = gc1[colh] * (CsS[r][j] - mc[j]) * scC[j] + bc1[colh];
        float h = sigm(OsS[r][j]) * tanhf(cn);
        h1out[r * Hn + colh] = h;
        g_H1[(r * Tn + t) * Hn + colh] = h;   // output row order (b*T + t)
    }
}

// ------------------------------ launch ------------------------------------
extern "C" void kernel_launch(void* const* d_in, const int* in_sizes, int n_in,
                              void* d_out, int out_size) {
    const int*   inp = (const int*)  d_in[0];
    const float* emb = (const float*)d_in[1];
    const float* Wx0 = (const float*)d_in[2];
    const float* Wh0 = (const float*)d_in[3];
    const float* b0  = (const float*)d_in[4];
    const float* gx0 = (const float*)d_in[5];
    const float* gh0 = (const float*)d_in[6];
    const float* gc0 = (const float*)d_in[7];
    const float* bc0 = (const float*)d_in[8];
    const float* Wx1 = (const float*)d_in[9];
    const float* Wh1 = (const float*)d_in[10];
    const float* b1  = (const float*)d_in[11];
    const float* gx1 = (const float*)d_in[12];
    const float* gh1 = (const float*)d_in[13];
    const float* gc1 = (const float*)d_in[14];
    const float* bc1 = (const float*)d_in[15];
    const float* Wp  = (const float*)d_in[16];
    const float* bp  = (const float*)d_in[17];
    const float* sw  = (const float*)d_in[18];
    const float* sb  = (const float*)d_in[19];
    float* out = (float*)d_out;

    float *pX, *pGX0, *pH1, *pY;
    cudaGetSymbolAddress((void**)&pX,   g_X);
    cudaGetSymbolAddress((void**)&pGX0, g_GX0);
    cudaGetSymbolAddress((void**)&pH1,  g_H1);
    cudaGetSymbolAddress((void**)&pY,   g_Y);

    k_init<<<256, 256>>>();
    k_embed<<<Tn * Bn, 256>>>(inp, emb);

    // GX0 = X @ Wx0   [8192, 4096], K=256
    k_gemm<<<dim3(FH / 64, (Tn * Bn) / 128), 256>>>(pX, Wx0, nullptr, pGX0,
                                                    Tn * Bn, FH, NUn);
    // normalize GX0 in place (per-timestep batch BN, gx0 folded in)
    k_bnx<<<(Tn * FH) / 256, 256>>>(gx0);

    for (int t = 0; t < Tn; t++) {
        k_step0<<<128, 256>>>(t, Wh0, b0, gh0, gc0, bc0);
        k_step1<<<128, 256>>>(t, Wx1, Wh1, b1, gx1, gh1, gc1, bc1);
    }

    // Y = H1 @ Wp + bp   [8192, 256], K=1024
    k_gemm<<<dim3(NUn / 64, (Tn * Bn) / 128), 256>>>(pH1, Wp, bp, pY,
                                                     Tn * Bn, NUn, Hn);
    // logits = Y @ softmax_w + softmax_b   [8192, 8000], K=256
    k_gemm<<<dim3(Vn / 64, (Tn * Bn) / 128), 256>>>(pY, sw, sb, out,
                                                    Tn * Bn, Vn, NUn);
}